// round 9
// baseline (speedup 1.0000x reference)
#include <cuda_runtime.h>
#include <cuda_fp16.h>
#include <math.h>
#include <stdint.h>

// Problem constants
#define BATCH 4
#define CH    512
#define HW    4096
#define NG    32
#define CPG   (CH / NG)     // 16
#define GN_ELEMS (CPG * HW) // 65536
#define WSZ   (CH * CH)     // 262144

// ---------------- scratch ---------------------------------------------------
__device__ __half g_xn[BATCH * HW * CH];            // xn^T  [hw][c]
__device__ __half g_qk[(size_t)BATCH * HW * 1024];  // [hw][q(512)|k(512)]
__device__ __half g_v [BATCH * CH * HW];            // v     [c][hw]
__device__ __half g_ao[BATCH * HW * CH];            // ao^T  [hw][c]
__device__ __half g_S [(size_t)BATCH * HW * HW];    // E = exp(scores)
__device__ __half g_wqk[2 * WSZ];                   // [wq rows | wk rows]
__device__ __half g_wv[WSZ];
__device__ __half g_wo[WSZ];
__device__ float  g_bqk[1024];                      // [bq | bk]
__device__ float  g_l  [BATCH * HW];                // rowsum(E)

// ---------------- setup: weights->fp16, pack qk, zero rowsums ---------------
__global__ __launch_bounds__(256) void setup_kernel(
    const float* __restrict__ wq, const float* __restrict__ wk,
    const float* __restrict__ wv, const float* __restrict__ wo,
    const float* __restrict__ bq, const float* __restrict__ bk,
    __half* __restrict__ wqk, __half* __restrict__ wvh,
    __half* __restrict__ woh, float* __restrict__ bqk,
    float* __restrict__ lsum)
{
    int i = blockIdx.x * 256 + threadIdx.x;
    if (i < WSZ) {
        wqk[i]       = __float2half(wq[i]);
        wqk[WSZ + i] = __float2half(wk[i]);
        wvh[i]       = __float2half(wv[i]);
        woh[i]       = __float2half(wo[i]);
    }
    if (i < 512) { bqk[i] = bq[i]; bqk[512 + i] = bk[i]; }
    if (i < BATCH * HW) lsum[i] = 0.f;
}

// ---------------- GroupNorm -> transposed fp16 output ----------------------
__global__ __launch_bounds__(512) void gn_t_kernel(
    const float* __restrict__ x, const float* __restrict__ gamma,
    const float* __restrict__ beta, __half* __restrict__ xnT)
{
    const int bg = blockIdx.x;
    const int b  = bg / NG;
    const int g  = bg % NG;
    const float* xp = x + ((size_t)b * CH + (size_t)g * CPG) * HW;

    float sum = 0.f, sumsq = 0.f;
    for (int i = threadIdx.x; i < GN_ELEMS; i += 512) {
        float v = xp[i];
        sum += v; sumsq += v * v;
    }
    __shared__ float s1[16], s2[16];
    int lane = threadIdx.x & 31, wid = threadIdx.x >> 5;
    #pragma unroll
    for (int o = 16; o > 0; o >>= 1) {
        sum   += __shfl_xor_sync(0xffffffff, sum, o);
        sumsq += __shfl_xor_sync(0xffffffff, sumsq, o);
    }
    if (lane == 0) { s1[wid] = sum; s2[wid] = sumsq; }
    __syncthreads();
    if (wid == 0) {
        float a = (lane < 16) ? s1[lane] : 0.f;
        float c = (lane < 16) ? s2[lane] : 0.f;
        #pragma unroll
        for (int o = 16; o > 0; o >>= 1) {
            a += __shfl_xor_sync(0xffffffff, a, o);
            c += __shfl_xor_sync(0xffffffff, c, o);
        }
        if (lane == 0) { s1[0] = a; s2[0] = c; }
    }
    __syncthreads();
    const float inv_n = 1.0f / (float)GN_ELEMS;
    const float mean  = s1[0] * inv_n;
    const float var   = s2[0] * inv_n - mean * mean;
    const float rstd  = rsqrtf(var + 1e-6f);

    float ga[CPG], be[CPG];
    #pragma unroll
    for (int c = 0; c < CPG; c++) {
        float gm = gamma[g * CPG + c];
        ga[c] = gm * rstd;
        be[c] = beta[g * CPG + c] - mean * gm * rstd;
    }
    __half* op = xnT + (size_t)b * HW * CH + g * CPG;
    for (int p = threadIdx.x; p < HW; p += 512) {
        __half h[16];
        #pragma unroll
        for (int c = 0; c < CPG; c++)
            h[c] = __float2half(xp[(size_t)c * HW + p] * ga[c] + be[c]);
        uint4* d = reinterpret_cast<uint4*>(op + (size_t)p * CH);
        d[0] = *reinterpret_cast<uint4*>(&h[0]);
        d[1] = *reinterpret_cast<uint4*>(&h[8]);
    }
}

// ---------------- fp16 GEMM: all operands K-major ---------------------------
// C[m,n] = epi( alpha * sum_k A[m][k]*B[n][k] )
// CTA tile 128x128, 4 warps (2m x 2n), warp tile 64x64, BK=64.
// 2-stage cp.async pipeline, 2 CTAs/SM (128 threads).

#define BM 128
#define BN 128
#define BK 64
#define STRH 72      // rows of 64 halves, pad 8

__device__ __forceinline__ void cp16(void* dst, const void* src) {
    unsigned saddr = (unsigned)__cvta_generic_to_shared(dst);
    asm volatile("cp.async.cg.shared.global [%0], [%1], 16;"
                 :: "r"(saddr), "l"(src));
}
__device__ __forceinline__ void ldsm_x4(unsigned& r0, unsigned& r1,
                                        unsigned& r2, unsigned& r3,
                                        unsigned saddr) {
    asm volatile("ldmatrix.sync.aligned.m8n8.x4.shared.b16 {%0,%1,%2,%3}, [%4];"
                 : "=r"(r0), "=r"(r1), "=r"(r2), "=r"(r3) : "r"(saddr));
}
__device__ __forceinline__ void mma16816(
    float& c0, float& c1, float& c2, float& c3,
    unsigned a0, unsigned a1, unsigned a2, unsigned a3,
    unsigned b0, unsigned b1)
{
    asm volatile(
        "mma.sync.aligned.m16n8k16.row.col.f32.f16.f16.f32 "
        "{%0,%1,%2,%3}, {%4,%5,%6,%7}, {%8,%9}, {%0,%1,%2,%3};"
        : "+f"(c0), "+f"(c1), "+f"(c2), "+f"(c3)
        : "r"(a0), "r"(a1), "r"(a2), "r"(a3), "r"(b0), "r"(b1));
}

template<bool OUT_HALF, bool DO_EXP>
__global__ __launch_bounds__(128, 2) void gemm_k(
    const __half* __restrict__ A, const __half* __restrict__ B,
    void* __restrict__ Cv,
    int M, int N, int K, int lda, int ldb,
    long long aB, long long bB, long long cB,
    float alpha, const float* __restrict__ bias_m,
    const float* __restrict__ bias_n,
    const float* __restrict__ ldiv,
    float* __restrict__ rowsum,
    const float* __restrict__ resid)
{
    extern __shared__ __half smh[];
    constexpr int TS_H = BM * STRH;        // 9216 halves per tile
    __half* Asb[2] = { smh,        smh + 2 * TS_H };
    __half* Bsb[2] = { smh + TS_H, smh + 3 * TS_H };

    const int tid  = threadIdx.x;
    const int lane = tid & 31;
    const int warp = tid >> 5;
    const int wm   = warp >> 1;        // 0..1
    const int wn   = warp & 1;         // 0..1
    const int g    = lane >> 2;        // 0..7
    const int t    = lane & 3;         // 0..3

    const int bm = blockIdx.y * BM;
    const int bn = blockIdx.x * BN;
    const int bz = blockIdx.z;
    A += (size_t)bz * aB;
    B += (size_t)bz * bB;

    // loaders: 128 rows x 64 halves = 1024 16B chunks, 8/thread
    auto issueA = [&](__half* as, int k0) {
        #pragma unroll
        for (int tt = 0; tt < 8; tt++) {
            int v = tid + tt * 128;
            int r = v >> 3, ko = (v & 7) << 3;
            cp16(&as[r * STRH + ko], &A[(size_t)(bm + r) * lda + k0 + ko]);
        }
    };
    auto issueB = [&](__half* bs, int k0) {
        #pragma unroll
        for (int tt = 0; tt < 8; tt++) {
            int v = tid + tt * 128;
            int r = v >> 3, ko = (v & 7) << 3;
            cp16(&bs[r * STRH + ko], &B[(size_t)(bn + r) * ldb + k0 + ko]);
        }
    };

    // ldmatrix per-lane bases (halves) — proven K-contig patterns
    const int aBase = (wm * 64 + (lane & 15)) * STRH + ((lane >> 4) << 3);
    const int bBase = (wn * 64 + (lane & 7) + ((lane >> 4) << 3)) * STRH
                      + (((lane >> 3) & 1) << 3);

    float acc[4][8][4];
    #pragma unroll
    for (int mi = 0; mi < 4; mi++)
        #pragma unroll
        for (int ni = 0; ni < 8; ni++)
            #pragma unroll
            for (int r = 0; r < 4; r++) acc[mi][ni][r] = 0.f;

    const int KT = K / BK;
    issueA(Asb[0], 0);
    issueB(Bsb[0], 0);
    asm volatile("cp.async.commit_group;");

    for (int kt = 0; kt < KT; kt++) {
        if (kt + 1 < KT) {
            issueA(Asb[(kt + 1) & 1], (kt + 1) * BK);
            issueB(Bsb[(kt + 1) & 1], (kt + 1) * BK);
            asm volatile("cp.async.commit_group;");
            asm volatile("cp.async.wait_group 1;");
        } else {
            asm volatile("cp.async.wait_group 0;");
        }
        __syncthreads();

        __half* as = Asb[kt & 1];
        __half* bs = Bsb[kt & 1];
        unsigned asm_base = (unsigned)__cvta_generic_to_shared(as);
        unsigned bsm_base = (unsigned)__cvta_generic_to_shared(bs);

        #pragma unroll
        for (int kk = 0; kk < BK; kk += 16) {
            unsigned af[4][4], bf[8][2];
            #pragma unroll
            for (int mi = 0; mi < 4; mi++)
                ldsm_x4(af[mi][0], af[mi][1], af[mi][2], af[mi][3],
                        asm_base + 2u * (aBase + mi * 16 * STRH + kk));
            #pragma unroll
            for (int nj = 0; nj < 4; nj++) {
                unsigned r0, r1, r2, r3;
                ldsm_x4(r0, r1, r2, r3,
                        bsm_base + 2u * (bBase + nj * 16 * STRH + kk));
                bf[2 * nj][0] = r0;     bf[2 * nj][1] = r1;
                bf[2 * nj + 1][0] = r2; bf[2 * nj + 1][1] = r3;
            }
            #pragma unroll
            for (int mi = 0; mi < 4; mi++)
                #pragma unroll
                for (int ni = 0; ni < 8; ni++)
                    mma16816(acc[mi][ni][0], acc[mi][ni][1],
                             acc[mi][ni][2], acc[mi][ni][3],
                             af[mi][0], af[mi][1], af[mi][2], af[mi][3],
                             bf[ni][0], bf[ni][1]);
        }
        __syncthreads();
    }

    // ---- epilogue ----
    #pragma unroll
    for (int mi = 0; mi < 4; mi++) {
        const int row0 = bm + wm * 64 + mi * 16 + g;
        const int row1 = row0 + 8;
        const float bv0 = bias_m ? bias_m[row0] : 0.f;
        const float bv1 = bias_m ? bias_m[row1] : 0.f;
        const float d0 = ldiv ? 1.0f / ldiv[(size_t)bz * M + row0] : 1.f;
        const float d1 = ldiv ? 1.0f / ldiv[(size_t)bz * M + row1] : 1.f;
        float s0 = 0.f, s1 = 0.f;

        #pragma unroll
        for (int ni = 0; ni < 8; ni++) {
            const int col = bn + wn * 64 + ni * 8 + t * 2;
            float v0 = acc[mi][ni][0] * alpha;
            float v1 = acc[mi][ni][1] * alpha;
            float v2 = acc[mi][ni][2] * alpha;
            float v3 = acc[mi][ni][3] * alpha;
            if (DO_EXP) {
                v0 = __expf(v0); v1 = __expf(v1);
                v2 = __expf(v2); v3 = __expf(v3);
                s0 += v0 + v1; s1 += v2 + v3;
            }
            v0 = v0 * d0 + bv0; v1 = v1 * d0 + bv0;
            v2 = v2 * d1 + bv1; v3 = v3 * d1 + bv1;
            if (bias_n) {
                float2 b2 = *reinterpret_cast<const float2*>(&bias_n[col]);
                v0 += b2.x; v1 += b2.y; v2 += b2.x; v3 += b2.y;
            }
            if (OUT_HALF) {
                __half* C = (__half*)Cv + (size_t)bz * cB;
                *reinterpret_cast<__half2*>(&C[(size_t)row0 * N + col]) =
                    __floats2half2_rn(v0, v1);
                *reinterpret_cast<__half2*>(&C[(size_t)row1 * N + col]) =
                    __floats2half2_rn(v2, v3);
            } else {
                float* C = (float*)Cv + (size_t)bz * cB;
                float2 r0 = make_float2(v0, v1);
                float2 r1 = make_float2(v2, v3);
                if (resid) {
                    const float* rs = resid + (size_t)bz * cB;
                    float2 q0 = *reinterpret_cast<const float2*>(&rs[(size_t)row0 * N + col]);
                    float2 q1 = *reinterpret_cast<const float2*>(&rs[(size_t)row1 * N + col]);
                    r0.x += q0.x; r0.y += q0.y;
                    r1.x += q1.x; r1.y += q1.y;
                }
                *reinterpret_cast<float2*>(&C[(size_t)row0 * N + col]) = r0;
                *reinterpret_cast<float2*>(&C[(size_t)row1 * N + col]) = r1;
            }
        }
        if (DO_EXP) {
            s0 += __shfl_xor_sync(0xffffffff, s0, 1);
            s0 += __shfl_xor_sync(0xffffffff, s0, 2);
            s1 += __shfl_xor_sync(0xffffffff, s1, 1);
            s1 += __shfl_xor_sync(0xffffffff, s1, 2);
            if (t == 0) {
                atomicAdd(&rowsum[(size_t)bz * M + row0], s0);
                atomicAdd(&rowsum[(size_t)bz * M + row1], s1);
            }
        }
    }
}

// ---------------- launch -----------------------------------------------------
extern "C" void kernel_launch(void* const* d_in, const int* in_sizes, int n_in,
                              void* d_out, int out_size)
{
    const float* x    = (const float*)d_in[0];
    const float* gn_w = (const float*)d_in[1];
    const float* gn_b = (const float*)d_in[2];
    const float* wq   = (const float*)d_in[3];
    const float* bq   = (const float*)d_in[4];
    const float* wk   = (const float*)d_in[5];
    const float* bk   = (const float*)d_in[6];
    const float* wv   = (const float*)d_in[7];
    const float* bv   = (const float*)d_in[8];
    const float* wo   = (const float*)d_in[9];
    const float* bo   = (const float*)d_in[10];
    float* out = (float*)d_out;

    __half *xn, *qk, *v, *ao, *S, *wqkh, *wvh, *woh;
    float *bqk, *lsum;
    cudaGetSymbolAddress((void**)&xn, g_xn);
    cudaGetSymbolAddress((void**)&qk, g_qk);
    cudaGetSymbolAddress((void**)&v,  g_v);
    cudaGetSymbolAddress((void**)&ao, g_ao);
    cudaGetSymbolAddress((void**)&S,  g_S);
    cudaGetSymbolAddress((void**)&wqkh, g_wqk);
    cudaGetSymbolAddress((void**)&wvh,  g_wv);
    cudaGetSymbolAddress((void**)&woh,  g_wo);
    cudaGetSymbolAddress((void**)&bqk,  g_bqk);
    cudaGetSymbolAddress((void**)&lsum, g_l);

    const long long chw  = (long long)CH * HW;
    const long long qkhw = (long long)HW * 1024;
    const long long shw  = (long long)HW * HW;
    const float scale = 1.0f / sqrtf((float)CH);

    const int SMEM = 4 * (BM * STRH) * 2;   // 73728 B
    cudaFuncSetAttribute(gemm_k<true, false>,
        cudaFuncAttributeMaxDynamicSharedMemorySize, SMEM);
    cudaFuncSetAttribute(gemm_k<true, true>,
        cudaFuncAttributeMaxDynamicSharedMemorySize, SMEM);
    cudaFuncSetAttribute(gemm_k<false, false>,
        cudaFuncAttributeMaxDynamicSharedMemorySize, SMEM);

    // 0. setup: weights->fp16 (packed qk), bias pack, zero rowsums
    setup_kernel<<<(WSZ + 255) / 256, 256>>>(wq, wk, wv, wo, bq, bk,
                                             wqkh, wvh, woh, bqk, lsum);

    // 1. GroupNorm -> xn^T [hw][c]
    gn_t_kernel<<<BATCH * NG, 512>>>(x, gn_w, gn_b, xn);

    // 2. qk[i][:] = xnT[i][:]·wqk^T + bqk  (M=4096, N=1024)
    {
        dim3 grid(1024 / BN, HW / BM, BATCH);
        gemm_k<true, false><<<grid, 128, SMEM>>>(xn, wqkh, qk, HW, 1024, CH,
            CH, CH, chw, 0, qkhw, 1.0f, nullptr, bqk, nullptr, nullptr, nullptr);
    }
    // 3. v (M=512, N=4096)
    {
        dim3 grid(HW / BN, CH / BM, BATCH);
        gemm_k<true, false><<<grid, 128, SMEM>>>(wvh, xn, v, CH, HW, CH, CH, CH,
            0, chw, chw, 1.0f, bv, nullptr, nullptr, nullptr, nullptr);
    }

    // 4. E = exp(scale * q·k^T); rowsum -> l  (M=N=4096, K=512)
    {
        dim3 grid(HW / BN, HW / BM, BATCH);
        gemm_k<true, true><<<grid, 128, SMEM>>>(qk, qk + 512, S, HW, HW, CH,
            1024, 1024, qkhw, qkhw, shw, scale,
            nullptr, nullptr, nullptr, lsum, nullptr);
    }

    // 5. aoT = (1/l) * E·v^T  (M=4096, N=512, K=4096)
    {
        dim3 grid(CH / BN, HW / BM, BATCH);
        gemm_k<true, false><<<grid, 128, SMEM>>>(S, v, ao, HW, CH, HW, HW, HW,
            shw, chw, chw, 1.0f, nullptr, nullptr, lsum, nullptr, nullptr);
    }

    // 6. out = wo·aoT^T + bo + x  (M=512, N=4096, fp32)
    {
        dim3 grid(HW / BN, CH / BM, BATCH);
        gemm_k<false, false><<<grid, 128, SMEM>>>(woh, ao, out, CH, HW, CH, CH, CH,
            0, chw, chw, 1.0f, bo, nullptr, nullptr, nullptr, x);
    }
}

// round 10
// speedup vs baseline: 1.4225x; 1.4225x over previous
#include <cuda_runtime.h>
#include <cuda_fp16.h>
#include <math.h>
#include <stdint.h>

// Problem constants
#define BATCH 4
#define CH    512
#define HW    4096
#define NG    32
#define CPG   (CH / NG)     // 16
#define GN_ELEMS (CPG * HW) // 65536
#define WSZ   (CH * CH)     // 262144

// ---------------- scratch ---------------------------------------------------
__device__ __half g_xn[BATCH * HW * CH];            // xn^T  [hw][c]
__device__ __half g_qk[(size_t)BATCH * HW * 1024];  // [hw][q(512)|k(512)]
__device__ __half g_v [BATCH * CH * HW];            // v     [c][hw]
__device__ __half g_ao[BATCH * HW * CH];            // ao^T  [hw][c]
__device__ __half g_S [(size_t)BATCH * HW * HW];    // E = exp(scores)
__device__ __half g_wqk[2 * WSZ];                   // [wq rows | wk rows]
__device__ __half g_wv[WSZ];
__device__ __half g_wo[WSZ];
__device__ float  g_bqk[1024];                      // [bq | bk]
__device__ float  g_l  [BATCH * HW];                // rowsum(E)

// ---------------- setup: weights->fp16, pack qk, zero rowsums ---------------
__global__ __launch_bounds__(256) void setup_kernel(
    const float* __restrict__ wq, const float* __restrict__ wk,
    const float* __restrict__ wv, const float* __restrict__ wo,
    const float* __restrict__ bq, const float* __restrict__ bk,
    __half* __restrict__ wqk, __half* __restrict__ wvh,
    __half* __restrict__ woh, float* __restrict__ bqk,
    float* __restrict__ lsum)
{
    int i = blockIdx.x * 256 + threadIdx.x;
    if (i < WSZ) {
        wqk[i]       = __float2half(wq[i]);
        wqk[WSZ + i] = __float2half(wk[i]);
        wvh[i]       = __float2half(wv[i]);
        woh[i]       = __float2half(wo[i]);
    }
    if (i < 512) { bqk[i] = bq[i]; bqk[512 + i] = bk[i]; }
    if (i < BATCH * HW) lsum[i] = 0.f;
}

// ---------------- GroupNorm -> transposed fp16 output ----------------------
__global__ __launch_bounds__(512) void gn_t_kernel(
    const float* __restrict__ x, const float* __restrict__ gamma,
    const float* __restrict__ beta, __half* __restrict__ xnT)
{
    const int bg = blockIdx.x;
    const int b  = bg / NG;
    const int g  = bg % NG;
    const float* xp = x + ((size_t)b * CH + (size_t)g * CPG) * HW;

    float sum = 0.f, sumsq = 0.f;
    for (int i = threadIdx.x; i < GN_ELEMS; i += 512) {
        float v = xp[i];
        sum += v; sumsq += v * v;
    }
    __shared__ float s1[16], s2[16];
    int lane = threadIdx.x & 31, wid = threadIdx.x >> 5;
    #pragma unroll
    for (int o = 16; o > 0; o >>= 1) {
        sum   += __shfl_xor_sync(0xffffffff, sum, o);
        sumsq += __shfl_xor_sync(0xffffffff, sumsq, o);
    }
    if (lane == 0) { s1[wid] = sum; s2[wid] = sumsq; }
    __syncthreads();
    if (wid == 0) {
        float a = (lane < 16) ? s1[lane] : 0.f;
        float c = (lane < 16) ? s2[lane] : 0.f;
        #pragma unroll
        for (int o = 16; o > 0; o >>= 1) {
            a += __shfl_xor_sync(0xffffffff, a, o);
            c += __shfl_xor_sync(0xffffffff, c, o);
        }
        if (lane == 0) { s1[0] = a; s2[0] = c; }
    }
    __syncthreads();
    const float inv_n = 1.0f / (float)GN_ELEMS;
    const float mean  = s1[0] * inv_n;
    const float var   = s2[0] * inv_n - mean * mean;
    const float rstd  = rsqrtf(var + 1e-6f);

    float ga[CPG], be[CPG];
    #pragma unroll
    for (int c = 0; c < CPG; c++) {
        float gm = gamma[g * CPG + c];
        ga[c] = gm * rstd;
        be[c] = beta[g * CPG + c] - mean * gm * rstd;
    }
    __half* op = xnT + (size_t)b * HW * CH + g * CPG;
    for (int p = threadIdx.x; p < HW; p += 512) {
        __half h[16];
        #pragma unroll
        for (int c = 0; c < CPG; c++)
            h[c] = __float2half(xp[(size_t)c * HW + p] * ga[c] + be[c]);
        uint4* d = reinterpret_cast<uint4*>(op + (size_t)p * CH);
        d[0] = *reinterpret_cast<uint4*>(&h[0]);
        d[1] = *reinterpret_cast<uint4*>(&h[8]);
    }
}

// ---------------- fp16 GEMM: all operands K-major ---------------------------
// C[m,n] = epi( alpha * sum_k A[m][k]*B[n][k] )
// CTA tile 128x128, 8 warps (2m x 4n), warp tile 64x32, BK=64.
// 2-stage cp.async, SINGLE __syncthreads per K-tile, 2 CTAs/SM.

#define BM 128
#define BN 128
#define BK 64
#define STRH 72      // rows of 64 halves, pad 8

__device__ __forceinline__ void cp16(void* dst, const void* src) {
    unsigned saddr = (unsigned)__cvta_generic_to_shared(dst);
    asm volatile("cp.async.cg.shared.global [%0], [%1], 16;"
                 :: "r"(saddr), "l"(src));
}
__device__ __forceinline__ void ldsm_x4(unsigned& r0, unsigned& r1,
                                        unsigned& r2, unsigned& r3,
                                        unsigned saddr) {
    asm volatile("ldmatrix.sync.aligned.m8n8.x4.shared.b16 {%0,%1,%2,%3}, [%4];"
                 : "=r"(r0), "=r"(r1), "=r"(r2), "=r"(r3) : "r"(saddr));
}
__device__ __forceinline__ void mma16816(
    float& c0, float& c1, float& c2, float& c3,
    unsigned a0, unsigned a1, unsigned a2, unsigned a3,
    unsigned b0, unsigned b1)
{
    asm volatile(
        "mma.sync.aligned.m16n8k16.row.col.f32.f16.f16.f32 "
        "{%0,%1,%2,%3}, {%4,%5,%6,%7}, {%8,%9}, {%0,%1,%2,%3};"
        : "+f"(c0), "+f"(c1), "+f"(c2), "+f"(c3)
        : "r"(a0), "r"(a1), "r"(a2), "r"(a3), "r"(b0), "r"(b1));
}

template<bool OUT_HALF, bool DO_EXP>
__global__ __launch_bounds__(256, 2) void gemm_k(
    const __half* __restrict__ A, const __half* __restrict__ B,
    void* __restrict__ Cv,
    int M, int N, int K, int lda, int ldb,
    long long aB, long long bB, long long cB,
    float alpha, const float* __restrict__ bias_m,
    const float* __restrict__ bias_n,
    const float* __restrict__ ldiv,
    float* __restrict__ rowsum,
    const float* __restrict__ resid)
{
    extern __shared__ __half smh[];
    constexpr int TS_H = BM * STRH;        // 9216 halves per tile
    __half* Asb[2] = { smh,        smh + 2 * TS_H };
    __half* Bsb[2] = { smh + TS_H, smh + 3 * TS_H };

    const int tid  = threadIdx.x;
    const int lane = tid & 31;
    const int warp = tid >> 5;
    const int wm   = warp >> 2;        // 0..1
    const int wn   = warp & 3;         // 0..3
    const int g    = lane >> 2;        // 0..7
    const int t    = lane & 3;         // 0..3

    const int bm = blockIdx.y * BM;
    const int bn = blockIdx.x * BN;
    const int bz = blockIdx.z;
    A += (size_t)bz * aB;
    B += (size_t)bz * bB;

    auto issueA = [&](__half* as, int k0) {
        #pragma unroll
        for (int tt = 0; tt < 4; tt++) {
            int v = tid + tt * 256;
            int r = v >> 3, ko = (v & 7) << 3;
            cp16(&as[r * STRH + ko], &A[(size_t)(bm + r) * lda + k0 + ko]);
        }
    };
    auto issueB = [&](__half* bs, int k0) {
        #pragma unroll
        for (int tt = 0; tt < 4; tt++) {
            int v = tid + tt * 256;
            int r = v >> 3, ko = (v & 7) << 3;
            cp16(&bs[r * STRH + ko], &B[(size_t)(bn + r) * ldb + k0 + ko]);
        }
    };

    const int aBase = (wm * 64 + (lane & 15)) * STRH + ((lane >> 4) << 3);
    const int bBase = (wn * 32 + (lane & 7) + ((lane >> 4) << 3)) * STRH
                      + (((lane >> 3) & 1) << 3);

    float acc[4][4][4];
    #pragma unroll
    for (int mi = 0; mi < 4; mi++)
        #pragma unroll
        for (int ni = 0; ni < 4; ni++)
            #pragma unroll
            for (int r = 0; r < 4; r++) acc[mi][ni][r] = 0.f;

    const int KT = K / BK;
    issueA(Asb[0], 0);
    issueB(Bsb[0], 0);
    asm volatile("cp.async.commit_group;");

    for (int kt = 0; kt < KT; kt++) {
        asm volatile("cp.async.wait_group 0;");   // tile kt resident
        __syncthreads();                          // + all warps done with buf (kt+1)&1

        if (kt + 1 < KT) {                        // prefetch overlaps compute(kt)
            issueA(Asb[(kt + 1) & 1], (kt + 1) * BK);
            issueB(Bsb[(kt + 1) & 1], (kt + 1) * BK);
            asm volatile("cp.async.commit_group;");
        }

        __half* as = Asb[kt & 1];
        __half* bs = Bsb[kt & 1];
        unsigned asm_base = (unsigned)__cvta_generic_to_shared(as);
        unsigned bsm_base = (unsigned)__cvta_generic_to_shared(bs);

        #pragma unroll
        for (int kk = 0; kk < BK; kk += 16) {
            unsigned af[4][4], bf[4][2];
            #pragma unroll
            for (int mi = 0; mi < 4; mi++)
                ldsm_x4(af[mi][0], af[mi][1], af[mi][2], af[mi][3],
                        asm_base + 2u * (aBase + mi * 16 * STRH + kk));
            #pragma unroll
            for (int nj = 0; nj < 2; nj++) {
                unsigned r0, r1, r2, r3;
                ldsm_x4(r0, r1, r2, r3,
                        bsm_base + 2u * (bBase + nj * 16 * STRH + kk));
                bf[2 * nj][0] = r0;     bf[2 * nj][1] = r1;
                bf[2 * nj + 1][0] = r2; bf[2 * nj + 1][1] = r3;
            }
            #pragma unroll
            for (int mi = 0; mi < 4; mi++)
                #pragma unroll
                for (int ni = 0; ni < 4; ni++)
                    mma16816(acc[mi][ni][0], acc[mi][ni][1],
                             acc[mi][ni][2], acc[mi][ni][3],
                             af[mi][0], af[mi][1], af[mi][2], af[mi][3],
                             bf[ni][0], bf[ni][1]);
        }
    }

    // ---- epilogue ----
    #pragma unroll
    for (int mi = 0; mi < 4; mi++) {
        const int row0 = bm + wm * 64 + mi * 16 + g;
        const int row1 = row0 + 8;
        const float bv0 = bias_m ? bias_m[row0] : 0.f;
        const float bv1 = bias_m ? bias_m[row1] : 0.f;
        const float d0 = ldiv ? 1.0f / ldiv[(size_t)bz * M + row0] : 1.f;
        const float d1 = ldiv ? 1.0f / ldiv[(size_t)bz * M + row1] : 1.f;
        float s0 = 0.f, s1 = 0.f;

        #pragma unroll
        for (int ni = 0; ni < 4; ni++) {
            const int col = bn + wn * 32 + ni * 8 + t * 2;
            float v0 = acc[mi][ni][0] * alpha;
            float v1 = acc[mi][ni][1] * alpha;
            float v2 = acc[mi][ni][2] * alpha;
            float v3 = acc[mi][ni][3] * alpha;
            if (DO_EXP) {
                v0 = __expf(v0); v1 = __expf(v1);
                v2 = __expf(v2); v3 = __expf(v3);
                s0 += v0 + v1; s1 += v2 + v3;
            }
            v0 = v0 * d0 + bv0; v1 = v1 * d0 + bv0;
            v2 = v2 * d1 + bv1; v3 = v3 * d1 + bv1;
            if (bias_n) {
                float2 b2 = *reinterpret_cast<const float2*>(&bias_n[col]);
                v0 += b2.x; v1 += b2.y; v2 += b2.x; v3 += b2.y;
            }
            if (OUT_HALF) {
                __half* C = (__half*)Cv + (size_t)bz * cB;
                *reinterpret_cast<__half2*>(&C[(size_t)row0 * N + col]) =
                    __floats2half2_rn(v0, v1);
                *reinterpret_cast<__half2*>(&C[(size_t)row1 * N + col]) =
                    __floats2half2_rn(v2, v3);
            } else {
                float* C = (float*)Cv + (size_t)bz * cB;
                float2 r0 = make_float2(v0, v1);
                float2 r1 = make_float2(v2, v3);
                if (resid) {
                    const float* rs = resid + (size_t)bz * cB;
                    float2 q0 = *reinterpret_cast<const float2*>(&rs[(size_t)row0 * N + col]);
                    float2 q1 = *reinterpret_cast<const float2*>(&rs[(size_t)row1 * N + col]);
                    r0.x += q0.x; r0.y += q0.y;
                    r1.x += q1.x; r1.y += q1.y;
                }
                *reinterpret_cast<float2*>(&C[(size_t)row0 * N + col]) = r0;
                *reinterpret_cast<float2*>(&C[(size_t)row1 * N + col]) = r1;
            }
        }
        if (DO_EXP) {
            s0 += __shfl_xor_sync(0xffffffff, s0, 1);
            s0 += __shfl_xor_sync(0xffffffff, s0, 2);
            s1 += __shfl_xor_sync(0xffffffff, s1, 1);
            s1 += __shfl_xor_sync(0xffffffff, s1, 2);
            if (t == 0) {
                atomicAdd(&rowsum[(size_t)bz * M + row0], s0);
                atomicAdd(&rowsum[(size_t)bz * M + row1], s1);
            }
        }
    }
}

// ---------------- launch -----------------------------------------------------
extern "C" void kernel_launch(void* const* d_in, const int* in_sizes, int n_in,
                              void* d_out, int out_size)
{
    const float* x    = (const float*)d_in[0];
    const float* gn_w = (const float*)d_in[1];
    const float* gn_b = (const float*)d_in[2];
    const float* wq   = (const float*)d_in[3];
    const float* bq   = (const float*)d_in[4];
    const float* wk   = (const float*)d_in[5];
    const float* bk   = (const float*)d_in[6];
    const float* wv   = (const float*)d_in[7];
    const float* bv   = (const float*)d_in[8];
    const float* wo   = (const float*)d_in[9];
    const float* bo   = (const float*)d_in[10];
    float* out = (float*)d_out;

    __half *xn, *qk, *v, *ao, *S, *wqkh, *wvh, *woh;
    float *bqk, *lsum;
    cudaGetSymbolAddress((void**)&xn, g_xn);
    cudaGetSymbolAddress((void**)&qk, g_qk);
    cudaGetSymbolAddress((void**)&v,  g_v);
    cudaGetSymbolAddress((void**)&ao, g_ao);
    cudaGetSymbolAddress((void**)&S,  g_S);
    cudaGetSymbolAddress((void**)&wqkh, g_wqk);
    cudaGetSymbolAddress((void**)&wvh,  g_wv);
    cudaGetSymbolAddress((void**)&woh,  g_wo);
    cudaGetSymbolAddress((void**)&bqk,  g_bqk);
    cudaGetSymbolAddress((void**)&lsum, g_l);

    const long long chw  = (long long)CH * HW;
    const long long qkhw = (long long)HW * 1024;
    const long long shw  = (long long)HW * HW;
    const float scale = 1.0f / sqrtf((float)CH);

    const int SMEM = 4 * (BM * STRH) * 2;   // 73728 B
    cudaFuncSetAttribute(gemm_k<true, false>,
        cudaFuncAttributeMaxDynamicSharedMemorySize, SMEM);
    cudaFuncSetAttribute(gemm_k<true, true>,
        cudaFuncAttributeMaxDynamicSharedMemorySize, SMEM);
    cudaFuncSetAttribute(gemm_k<false, false>,
        cudaFuncAttributeMaxDynamicSharedMemorySize, SMEM);

    // 0. setup: weights->fp16 (packed qk), bias pack, zero rowsums
    setup_kernel<<<(WSZ + 255) / 256, 256>>>(wq, wk, wv, wo, bq, bk,
                                             wqkh, wvh, woh, bqk, lsum);

    // 1. GroupNorm -> xn^T [hw][c]
    gn_t_kernel<<<BATCH * NG, 512>>>(x, gn_w, gn_b, xn);

    // 2. qk[i][:] = xnT[i][:]·wqk^T + bqk  (M=4096, N=1024)
    {
        dim3 grid(1024 / BN, HW / BM, BATCH);
        gemm_k<true, false><<<grid, 256, SMEM>>>(xn, wqkh, qk, HW, 1024, CH,
            CH, CH, chw, 0, qkhw, 1.0f, nullptr, bqk, nullptr, nullptr, nullptr);
    }
    // 3. v (M=512, N=4096)
    {
        dim3 grid(HW / BN, CH / BM, BATCH);
        gemm_k<true, false><<<grid, 256, SMEM>>>(wvh, xn, v, CH, HW, CH, CH, CH,
            0, chw, chw, 1.0f, bv, nullptr, nullptr, nullptr, nullptr);
    }

    // 4. E = exp(scale * q·k^T); rowsum -> l  (M=N=4096, K=512)
    {
        dim3 grid(HW / BN, HW / BM, BATCH);
        gemm_k<true, true><<<grid, 256, SMEM>>>(qk, qk + 512, S, HW, HW, CH,
            1024, 1024, qkhw, qkhw, shw, scale,
            nullptr, nullptr, nullptr, lsum, nullptr);
    }

    // 5. aoT = (1/l) * E·v^T  (M=4096, N=512, K=4096)
    {
        dim3 grid(CH / BN, HW / BM, BATCH);
        gemm_k<true, false><<<grid, 256, SMEM>>>(S, v, ao, HW, CH, HW, HW, HW,
            shw, chw, chw, 1.0f, nullptr, nullptr, lsum, nullptr, nullptr);
    }

    // 6. out = wo·aoT^T + bo + x  (M=512, N=4096, fp32)
    {
        dim3 grid(HW / BN, CH / BM, BATCH);
        gemm_k<false, false><<<grid, 256, SMEM>>>(woh, ao, out, CH, HW, CH, CH, CH,
            0, chw, chw, 1.0f, bo, nullptr, nullptr, nullptr, x);
    }
}